// round 2
// baseline (speedup 1.0000x reference)
#include <cuda_runtime.h>

typedef unsigned long long u64;

#define TPB 256
#define STRIDE10 41   // odd stride -> conflict-free scalar LDS (gcd(41,32)=1)
#define STRIDE8  33

// ---- packed f32x2 helpers ----
__device__ __forceinline__ u64 pk2(float lo, float hi) {
    u64 r; asm("mov.b64 %0,{%1,%2};" : "=l"(r) : "f"(lo), "f"(hi)); return r;
}
__device__ __forceinline__ float2 unpk(u64 v) {
    float2 f; asm("mov.b64 {%0,%1},%2;" : "=f"(f.x), "=f"(f.y) : "l"(v)); return f;
}
__device__ __forceinline__ u64 fma2(u64 a, u64 b, u64 c) {
    u64 d; asm("fma.rn.f32x2 %0,%1,%2,%3;" : "=l"(d) : "l"(a), "l"(b), "l"(c)); return d;
}
__device__ __forceinline__ u64 relu2(u64 v) {
    float2 f = unpk(v);
    return pk2(fmaxf(f.x, 0.f), fmaxf(f.y, 0.f));
}

// ---- shared weight layout (float2-duplicated), offsets in u64 units ----
#define O_EW1 0
#define O_EB1 100
#define O_EW2 110
#define O_EB2 210
#define O_EW3 220
#define O_EB3 230
#define O_XW1 231
#define O_XB1 295
#define O_XW2 303
#define O_XB2 367
#define O_XW3 375
#define O_XB3 383
#define O_CW1 384
#define O_CB1 484
#define O_CW2 494
#define O_CB2 594
#define O_CW3 604
#define O_CB3 614
#define O_NW  615
#define O_NB  616
#define NWTS  617

// 3-layer MLP over both slice-pairs, packed f32x2 (lane0 = slice 2p, lane1 = slice 2p+1).
// Returns sum over all 4 slices of the scalar MLP output.
template <int D>
__device__ __forceinline__ float mlp_sum4(const float* __restrict__ xe,
                                          const u64* __restrict__ w1, const u64* __restrict__ b1,
                                          const u64* __restrict__ w2, const u64* __restrict__ b2,
                                          const u64* __restrict__ w3, const u64* __restrict__ b3) {
    float total = 0.f;
#pragma unroll
    for (int p = 0; p < 2; ++p) {
        const float* xa = xe + (2 * p + 0) * D;
        const float* xb = xe + (2 * p + 1) * D;
        u64 x[D], h[D];
#pragma unroll
        for (int i = 0; i < D; i++) x[i] = pk2(xa[i], xb[i]);
        // layer 1 + relu
#pragma unroll
        for (int o = 0; o < D; o++) {
            u64 a = b1[o];
#pragma unroll
            for (int i = 0; i < D; i++) a = fma2(x[i], w1[o * D + i], a);
            h[o] = relu2(a);
        }
        // layer 2 + relu (reuse x as h2)
#pragma unroll
        for (int o = 0; o < D; o++) {
            u64 a = b2[o];
#pragma unroll
            for (int i = 0; i < D; i++) a = fma2(h[i], w2[o * D + i], a);
            x[o] = relu2(a);
        }
        // layer 3 (linear, out dim 1)
        u64 a = b3[0];
#pragma unroll
        for (int i = 0; i < D; i++) a = fma2(x[i], w3[i], a);
        float2 f = unpk(a);
        total += f.x + f.y;
    }
    return total;
}

// Coalesced stage of 256 elements x 40 floats into shared at stride 41.
__device__ __forceinline__ void stage40(const float* __restrict__ g, float* __restrict__ s, int tid) {
    const float4* g4 = (const float4*)g;
#pragma unroll
    for (int k = 0; k < 10; k++) {
        int f = k * TPB + tid;                 // 0..2559 float4s
        float4 v = g4[f];
        int elem = f / 10;
        int j = f - elem * 10;
        float* d = s + elem * STRIDE10 + j * 4;
        d[0] = v.x; d[1] = v.y; d[2] = v.z; d[3] = v.w;
    }
}

// Coalesced stage of 256 elements x 32 floats into shared at stride 33.
__device__ __forceinline__ void stage32(const float* __restrict__ g, float* __restrict__ s, int tid) {
    const float4* g4 = (const float4*)g;
#pragma unroll
    for (int k = 0; k < 8; k++) {
        int f = k * TPB + tid;                 // 0..2047 float4s
        float4 v = g4[f];
        int elem = f >> 3;
        int j = f & 7;
        float* d = s + elem * STRIDE8 + j * 4;
        d[0] = v.x; d[1] = v.y; d[2] = v.z; d[3] = v.w;
    }
}

__global__ __launch_bounds__(TPB, 3)
void osero_kernel(const float* __restrict__ edge, const float* __restrict__ cross,
                  const float* __restrict__ corner, const float* __restrict__ cn,
                  const float* __restrict__ eW1, const float* __restrict__ eb1,
                  const float* __restrict__ eW2, const float* __restrict__ eb2,
                  const float* __restrict__ eW3, const float* __restrict__ eb3,
                  const float* __restrict__ xW1, const float* __restrict__ xb1,
                  const float* __restrict__ xW2, const float* __restrict__ xb2,
                  const float* __restrict__ xW3, const float* __restrict__ xb3,
                  const float* __restrict__ cW1, const float* __restrict__ cb1,
                  const float* __restrict__ cW2, const float* __restrict__ cb2,
                  const float* __restrict__ cW3, const float* __restrict__ cb3,
                  const float* __restrict__ nW, const float* __restrict__ nb,
                  float* __restrict__ out) {
    __shared__ u64 swts[NWTS];
    __shared__ float sbuf[TPB * STRIDE10];   // 10496 floats = 41984 B

    const int tid = threadIdx.x;
    const long e0 = (long)blockIdx.x * TPB;

    // ---- stage weights, duplicated into both f32x2 lanes ----
    {
        auto cp = [&](int off, const float* src, int n) {
            for (int i = tid; i < n; i += TPB) { float v = src[i]; swts[off + i] = pk2(v, v); }
        };
        cp(O_EW1, eW1, 100); cp(O_EB1, eb1, 10);
        cp(O_EW2, eW2, 100); cp(O_EB2, eb2, 10);
        cp(O_EW3, eW3, 10);  cp(O_EB3, eb3, 1);
        cp(O_XW1, xW1, 64);  cp(O_XB1, xb1, 8);
        cp(O_XW2, xW2, 64);  cp(O_XB2, xb2, 8);
        cp(O_XW3, xW3, 8);   cp(O_XB3, xb3, 1);
        cp(O_CW1, cW1, 100); cp(O_CB1, cb1, 10);
        cp(O_CW2, cW2, 100); cp(O_CB2, cb2, 10);
        cp(O_CW3, cW3, 10);  cp(O_CB3, cb3, 1);
        cp(O_NW, nW, 1);     cp(O_NB, nb, 1);
    }

    float acc;

    // ---- EDGE ----
    stage40(edge + e0 * 40, sbuf, tid);
    __syncthreads();   // covers weights + edge staging
    acc = mlp_sum4<10>(sbuf + tid * STRIDE10,
                       swts + O_EW1, swts + O_EB1, swts + O_EW2,
                       swts + O_EB2, swts + O_EW3, swts + O_EB3);
    __syncthreads();

    // ---- CROSS ----
    stage32(cross + e0 * 32, sbuf, tid);
    __syncthreads();
    acc += mlp_sum4<8>(sbuf + tid * STRIDE8,
                       swts + O_XW1, swts + O_XB1, swts + O_XW2,
                       swts + O_XB2, swts + O_XW3, swts + O_XB3);
    __syncthreads();

    // ---- CORNER ----
    stage40(corner + e0 * 40, sbuf, tid);
    __syncthreads();
    acc += mlp_sum4<10>(sbuf + tid * STRIDE10,
                        swts + O_CW1, swts + O_CB1, swts + O_CW2,
                        swts + O_CB2, swts + O_CW3, swts + O_CB3);

    // ---- cn linear + output ----
    float2 nwv = unpk(swts[O_NW]);
    float2 nbv = unpk(swts[O_NB]);
    acc += cn[e0 + tid] * nwv.x + nbv.x;
    out[e0 + tid] = acc;
}

extern "C" void kernel_launch(void* const* d_in, const int* in_sizes, int n_in,
                              void* d_out, int out_size) {
    const float* edge   = (const float*)d_in[0];
    const float* cross  = (const float*)d_in[1];
    const float* corner = (const float*)d_in[2];
    const float* cn     = (const float*)d_in[3];
    const float* eW1 = (const float*)d_in[4];
    const float* eb1 = (const float*)d_in[5];
    const float* eW2 = (const float*)d_in[6];
    const float* eb2 = (const float*)d_in[7];
    const float* eW3 = (const float*)d_in[8];
    const float* eb3 = (const float*)d_in[9];
    const float* xW1 = (const float*)d_in[10];
    const float* xb1 = (const float*)d_in[11];
    const float* xW2 = (const float*)d_in[12];
    const float* xb2 = (const float*)d_in[13];
    const float* xW3 = (const float*)d_in[14];
    const float* xb3 = (const float*)d_in[15];
    const float* cW1 = (const float*)d_in[16];
    const float* cb1 = (const float*)d_in[17];
    const float* cW2 = (const float*)d_in[18];
    const float* cb2 = (const float*)d_in[19];
    const float* cW3 = (const float*)d_in[20];
    const float* cb3 = (const float*)d_in[21];
    const float* nW  = (const float*)d_in[22];
    const float* nb  = (const float*)d_in[23];

    int B = in_sizes[0] / 40;          // edge is [B,4,10]
    int blocks = B / TPB;              // B = 1048576 -> 4096 blocks

    osero_kernel<<<blocks, TPB>>>(edge, cross, corner, cn,
                                  eW1, eb1, eW2, eb2, eW3, eb3,
                                  xW1, xb1, xW2, xb2, xW3, xb3,
                                  cW1, cb1, cW2, cb2, cW3, cb3,
                                  nW, nb, (float*)d_out);
}

// round 5
// speedup vs baseline: 4.5197x; 4.5197x over previous
#include <cuda_runtime.h>

typedef unsigned long long u64;

#define TPB 256
// element strides in u64 units; 21 mod 16 = 5 (coprime 16) and 17 mod 16 = 1
// -> conflict-free LDS.64 across lanes
#define STRIDE10 21   // 20 u64 data (40 floats) + 1 pad
#define STRIDE8  17   // 16 u64 data (32 floats) + 1 pad

// ---- packed f32x2 helpers ----
__device__ __forceinline__ u64 pk2(float lo, float hi) {
    u64 r; asm("mov.b64 %0,{%1,%2};" : "=l"(r) : "f"(lo), "f"(hi)); return r;
}
__device__ __forceinline__ float2 unpk(u64 v) {
    float2 f; asm("mov.b64 {%0,%1},%2;" : "=f"(f.x), "=f"(f.y) : "l"(v)); return f;
}
__device__ __forceinline__ u64 fma2(u64 a, u64 b, u64 c) {
    u64 d; asm("fma.rn.f32x2 %0,%1,%2,%3;" : "=l"(d) : "l"(a), "l"(b), "l"(c)); return d;
}
__device__ __forceinline__ u64 relu2(u64 v) {
    float2 f = unpk(v);
    return pk2(fmaxf(f.x, 0.f), fmaxf(f.y, 0.f));
}

// ---- shared weight layout (float2-duplicated), offsets in u64 units ----
#define O_EW1 0
#define O_EB1 100
#define O_EW2 110
#define O_EB2 210
#define O_EW3 220
#define O_EB3 230
#define O_XW1 231
#define O_XB1 295
#define O_XW2 303
#define O_XB2 367
#define O_XW3 375
#define O_XB3 383
#define O_CW1 384
#define O_CB1 484
#define O_CW2 494
#define O_CB2 594
#define O_CW3 604
#define O_CB3 614
#define O_NW  615
#define O_NB  616
#define NWTS  617

// 3-layer MLP over 4 slices as two f32x2 pairs, interleaved so every weight
// LDS.64 is reused by both pairs. xe points at this element's staged u64 data:
// u64 index i*2+p holds {slice 2p, slice 2p+1} for input feature i.
template <int D>
__device__ __forceinline__ float mlp_sum4(const u64* __restrict__ xe,
                                          const u64* __restrict__ w1, const u64* __restrict__ b1,
                                          const u64* __restrict__ w2, const u64* __restrict__ b2,
                                          const u64* __restrict__ w3, const u64* __restrict__ b3) {
    u64 x0[D], x1[D], h0[D], h1[D];
#pragma unroll
    for (int i = 0; i < D; i++) { x0[i] = xe[i * 2]; x1[i] = xe[i * 2 + 1]; }
    // layer 1 + relu
#pragma unroll
    for (int o = 0; o < D; o++) {
        u64 b = b1[o], a0 = b, a1 = b;
#pragma unroll
        for (int i = 0; i < D; i++) {
            u64 w = w1[o * D + i];
            a0 = fma2(x0[i], w, a0);
            a1 = fma2(x1[i], w, a1);
        }
        h0[o] = relu2(a0); h1[o] = relu2(a1);
    }
    // layer 2 + relu (write back into x0/x1)
#pragma unroll
    for (int o = 0; o < D; o++) {
        u64 b = b2[o], a0 = b, a1 = b;
#pragma unroll
        for (int i = 0; i < D; i++) {
            u64 w = w2[o * D + i];
            a0 = fma2(h0[i], w, a0);
            a1 = fma2(h1[i], w, a1);
        }
        x0[o] = relu2(a0); x1[o] = relu2(a1);
    }
    // layer 3 (linear, out dim 1)
    u64 b = b3[0], a0 = b, a1 = b;
#pragma unroll
    for (int i = 0; i < D; i++) {
        u64 w = w3[i];
        a0 = fma2(x0[i], w, a0);
        a1 = fma2(x1[i], w, a1);
    }
    float2 f0 = unpk(a0), f1 = unpk(a1);
    return f0.x + f0.y + f1.x + f1.y;
}

// Coalesced stage of TPB elements x (4*D) floats from global into shared with
// pair-interleaved layout: element e, feature i, slice s -> e*STRIDE*2 + i*4 + s.
template <int D, int STRIDE>
__device__ __forceinline__ void stage(const float* __restrict__ g, float* __restrict__ s, int tid) {
    const float4* g4 = (const float4*)g;
#pragma unroll
    for (int k = 0; k < D; k++) {
        int f = k * TPB + tid;          // float4 index, consecutive across threads
        float4 v = g4[f];
        int elem = f / D;
        int j = f - elem * D;           // float4 within element (0..D-1)
        float vv[4] = {v.x, v.y, v.z, v.w};
        float* base = s + elem * (STRIDE * 2);
#pragma unroll
        for (int c = 0; c < 4; c++) {
            int within = j * 4 + c;     // 0..4D-1, slice-major in gmem
            int sl = within / D;
            int i  = within - sl * D;
            base[i * 4 + sl] = vv[c];
        }
    }
}

__global__ __launch_bounds__(TPB, 2)
void osero_kernel(const float* __restrict__ edge, const float* __restrict__ cross,
                  const float* __restrict__ corner, const float* __restrict__ cn,
                  const float* __restrict__ eW1, const float* __restrict__ eb1,
                  const float* __restrict__ eW2, const float* __restrict__ eb2,
                  const float* __restrict__ eW3, const float* __restrict__ eb3,
                  const float* __restrict__ xW1, const float* __restrict__ xb1,
                  const float* __restrict__ xW2, const float* __restrict__ xb2,
                  const float* __restrict__ xW3, const float* __restrict__ xb3,
                  const float* __restrict__ cW1, const float* __restrict__ cb1,
                  const float* __restrict__ cW2, const float* __restrict__ cb2,
                  const float* __restrict__ cW3, const float* __restrict__ cb3,
                  const float* __restrict__ nW, const float* __restrict__ nb,
                  float* __restrict__ out) {
    __shared__ u64 swts[NWTS];
    __shared__ u64 sbuf[TPB * STRIDE10];   // 5376 u64 = 43008 B

    const int tid = threadIdx.x;
    const long long e0 = (long long)blockIdx.x * TPB;

    // ---- stage weights, duplicated into both f32x2 lanes ----
    {
        auto cp = [&](int off, const float* src, int n) {
            for (int i = tid; i < n; i += TPB) { float v = src[i]; swts[off + i] = pk2(v, v); }
        };
        cp(O_EW1, eW1, 100); cp(O_EB1, eb1, 10);
        cp(O_EW2, eW2, 100); cp(O_EB2, eb2, 10);
        cp(O_EW3, eW3, 10);  cp(O_EB3, eb3, 1);
        cp(O_XW1, xW1, 64);  cp(O_XB1, xb1, 8);
        cp(O_XW2, xW2, 64);  cp(O_XB2, xb2, 8);
        cp(O_XW3, xW3, 8);   cp(O_XB3, xb3, 1);
        cp(O_CW1, cW1, 100); cp(O_CB1, cb1, 10);
        cp(O_CW2, cW2, 100); cp(O_CB2, cb2, 10);
        cp(O_CW3, cW3, 10);  cp(O_CB3, cb3, 1);
        cp(O_NW, nW, 1);     cp(O_NB, nb, 1);
    }

    float acc;

    // ---- EDGE ----
    stage<10, STRIDE10>(edge + e0 * 40, (float*)sbuf, tid);
    __syncthreads();   // covers weights + edge staging
    acc = mlp_sum4<10>(sbuf + tid * STRIDE10,
                       swts + O_EW1, swts + O_EB1, swts + O_EW2,
                       swts + O_EB2, swts + O_EW3, swts + O_EB3);
    __syncthreads();

    // ---- CROSS ----
    stage<8, STRIDE8>(cross + e0 * 32, (float*)sbuf, tid);
    __syncthreads();
    acc += mlp_sum4<8>(sbuf + tid * STRIDE8,
                       swts + O_XW1, swts + O_XB1, swts + O_XW2,
                       swts + O_XB2, swts + O_XW3, swts + O_XB3);
    __syncthreads();

    // ---- CORNER ----
    stage<10, STRIDE10>(corner + e0 * 40, (float*)sbuf, tid);
    __syncthreads();
    acc += mlp_sum4<10>(sbuf + tid * STRIDE10,
                        swts + O_CW1, swts + O_CB1, swts + O_CW2,
                        swts + O_CB2, swts + O_CW3, swts + O_CB3);

    // ---- cn linear + output ----
    float2 nwv = unpk(swts[O_NW]);
    float2 nbv = unpk(swts[O_NB]);
    acc += cn[e0 + tid] * nwv.x + nbv.x;
    out[e0 + tid] = acc;
}

extern "C" void kernel_launch(void* const* d_in, const int* in_sizes, int n_in,
                              void* d_out, int out_size) {
    const float* edge   = (const float*)d_in[0];
    const float* cross  = (const float*)d_in[1];
    const float* corner = (const float*)d_in[2];
    const float* cn     = (const float*)d_in[3];
    const float* eW1 = (const float*)d_in[4];
    const float* eb1 = (const float*)d_in[5];
    const float* eW2 = (const float*)d_in[6];
    const float* eb2 = (const float*)d_in[7];
    const float* eW3 = (const float*)d_in[8];
    const float* eb3 = (const float*)d_in[9];
    const float* xW1 = (const float*)d_in[10];
    const float* xb1 = (const float*)d_in[11];
    const float* xW2 = (const float*)d_in[12];
    const float* xb2 = (const float*)d_in[13];
    const float* xW3 = (const float*)d_in[14];
    const float* xb3 = (const float*)d_in[15];
    const float* cW1 = (const float*)d_in[16];
    const float* cb1 = (const float*)d_in[17];
    const float* cW2 = (const float*)d_in[18];
    const float* cb2 = (const float*)d_in[19];
    const float* cW3 = (const float*)d_in[20];
    const float* cb3 = (const float*)d_in[21];
    const float* nW  = (const float*)d_in[22];
    const float* nb  = (const float*)d_in[23];

    int B = in_sizes[0] / 40;          // edge is [B,4,10]
    int blocks = B / TPB;              // 4096

    osero_kernel<<<blocks, TPB>>>(edge, cross, corner, cn,
                                  eW1, eb1, eW2, eb2, eW3, eb3,
                                  xW1, xb1, xW2, xb2, xW3, xb3,
                                  cW1, cb1, cW2, cb2, cW3, cb3,
                                  nW, nb, (float*)d_out);
}

// round 6
// speedup vs baseline: 4.5249x; 1.0011x over previous
#include <cuda_runtime.h>

typedef unsigned long long u64;

#define TPB 256
// element strides in u64 units; 21 mod 16 = 5 (coprime 16) and 17 mod 16 = 1
// -> conflict-free LDS.64 across lanes
#define STRIDE10 21   // 20 u64 data (40 floats) + 1 pad
#define STRIDE8  17   // 16 u64 data (32 floats) + 1 pad

// ---- packed f32x2 helpers ----
__device__ __forceinline__ u64 pk2(float lo, float hi) {
    u64 r; asm("mov.b64 %0,{%1,%2};" : "=l"(r) : "f"(lo), "f"(hi)); return r;
}
__device__ __forceinline__ float2 unpk(u64 v) {
    float2 f; asm("mov.b64 {%0,%1},%2;" : "=f"(f.x), "=f"(f.y) : "l"(v)); return f;
}
__device__ __forceinline__ u64 fma2(u64 a, u64 b, u64 c) {
    u64 d; asm("fma.rn.f32x2 %0,%1,%2,%3;" : "=l"(d) : "l"(a), "l"(b), "l"(c)); return d;
}
__device__ __forceinline__ u64 relu2(u64 v) {
    float2 f = unpk(v);
    return pk2(fmaxf(f.x, 0.f), fmaxf(f.y, 0.f));
}

// ---- shared weight layout (float2-duplicated), offsets in u64 units ----
#define O_EW1 0
#define O_EB1 100
#define O_EW2 110
#define O_EB2 210
#define O_EW3 220
#define O_EB3 230
#define O_XW1 231
#define O_XB1 295
#define O_XW2 303
#define O_XB2 367
#define O_XW3 375
#define O_XB3 383
#define O_CW1 384
#define O_CB1 484
#define O_CW2 494
#define O_CB2 594
#define O_CW3 604
#define O_CB3 614
#define O_NW  615
#define O_NB  616
#define NWTS  617

// 3-layer MLP over 4 slices as two f32x2 pairs, interleaved so every weight
// LDS.64 is reused by both pairs. xe points at this element's staged u64 data:
// u64 index i*2+p holds {slice 2p, slice 2p+1} for input feature i.
template <int D>
__device__ __forceinline__ float mlp_sum4(const u64* __restrict__ xe,
                                          const u64* __restrict__ w1, const u64* __restrict__ b1,
                                          const u64* __restrict__ w2, const u64* __restrict__ b2,
                                          const u64* __restrict__ w3, const u64* __restrict__ b3) {
    u64 x0[D], x1[D], h0[D], h1[D];
#pragma unroll
    for (int i = 0; i < D; i++) { x0[i] = xe[i * 2]; x1[i] = xe[i * 2 + 1]; }
    // layer 1 + relu
#pragma unroll
    for (int o = 0; o < D; o++) {
        u64 b = b1[o], a0 = b, a1 = b;
#pragma unroll
        for (int i = 0; i < D; i++) {
            u64 w = w1[o * D + i];
            a0 = fma2(x0[i], w, a0);
            a1 = fma2(x1[i], w, a1);
        }
        h0[o] = relu2(a0); h1[o] = relu2(a1);
    }
    // layer 2 + relu (write back into x0/x1)
#pragma unroll
    for (int o = 0; o < D; o++) {
        u64 b = b2[o], a0 = b, a1 = b;
#pragma unroll
        for (int i = 0; i < D; i++) {
            u64 w = w2[o * D + i];
            a0 = fma2(h0[i], w, a0);
            a1 = fma2(h1[i], w, a1);
        }
        x0[o] = relu2(a0); x1[o] = relu2(a1);
    }
    // layer 3 (linear, out dim 1)
    u64 b = b3[0], a0 = b, a1 = b;
#pragma unroll
    for (int i = 0; i < D; i++) {
        u64 w = w3[i];
        a0 = fma2(x0[i], w, a0);
        a1 = fma2(x1[i], w, a1);
    }
    float2 f0 = unpk(a0), f1 = unpk(a1);
    return f0.x + f0.y + f1.x + f1.y;
}

// Coalesced stage of TPB elements x (4*D) floats from global into shared with
// pair-interleaved layout: element e, feature i, slice s -> e*STRIDE*2 + i*4 + s.
template <int D, int STRIDE>
__device__ __forceinline__ void stage(const float* __restrict__ g, float* __restrict__ s, int tid) {
    const float4* g4 = (const float4*)g;
#pragma unroll
    for (int k = 0; k < D; k++) {
        int f = k * TPB + tid;          // float4 index, consecutive across threads
        float4 v = g4[f];
        int elem = f / D;
        int j = f - elem * D;           // float4 within element (0..D-1)
        float vv[4] = {v.x, v.y, v.z, v.w};
        float* base = s + elem * (STRIDE * 2);
#pragma unroll
        for (int c = 0; c < 4; c++) {
            int within = j * 4 + c;     // 0..4D-1, slice-major in gmem
            int sl = within / D;
            int i  = within - sl * D;
            base[i * 4 + sl] = vv[c];
        }
    }
}

__global__ __launch_bounds__(TPB, 2)
void osero_kernel(const float* __restrict__ edge, const float* __restrict__ cross,
                  const float* __restrict__ corner, const float* __restrict__ cn,
                  const float* __restrict__ eW1, const float* __restrict__ eb1,
                  const float* __restrict__ eW2, const float* __restrict__ eb2,
                  const float* __restrict__ eW3, const float* __restrict__ eb3,
                  const float* __restrict__ xW1, const float* __restrict__ xb1,
                  const float* __restrict__ xW2, const float* __restrict__ xb2,
                  const float* __restrict__ xW3, const float* __restrict__ xb3,
                  const float* __restrict__ cW1, const float* __restrict__ cb1,
                  const float* __restrict__ cW2, const float* __restrict__ cb2,
                  const float* __restrict__ cW3, const float* __restrict__ cb3,
                  const float* __restrict__ nW, const float* __restrict__ nb,
                  float* __restrict__ out) {
    __shared__ u64 swts[NWTS];
    __shared__ u64 sbuf[TPB * STRIDE10];   // 5376 u64 = 43008 B

    const int tid = threadIdx.x;
    const long long e0 = (long long)blockIdx.x * TPB;

    // ---- stage weights, duplicated into both f32x2 lanes ----
    {
        auto cp = [&](int off, const float* src, int n) {
            for (int i = tid; i < n; i += TPB) { float v = src[i]; swts[off + i] = pk2(v, v); }
        };
        cp(O_EW1, eW1, 100); cp(O_EB1, eb1, 10);
        cp(O_EW2, eW2, 100); cp(O_EB2, eb2, 10);
        cp(O_EW3, eW3, 10);  cp(O_EB3, eb3, 1);
        cp(O_XW1, xW1, 64);  cp(O_XB1, xb1, 8);
        cp(O_XW2, xW2, 64);  cp(O_XB2, xb2, 8);
        cp(O_XW3, xW3, 8);   cp(O_XB3, xb3, 1);
        cp(O_CW1, cW1, 100); cp(O_CB1, cb1, 10);
        cp(O_CW2, cW2, 100); cp(O_CB2, cb2, 10);
        cp(O_CW3, cW3, 10);  cp(O_CB3, cb3, 1);
        cp(O_NW, nW, 1);     cp(O_NB, nb, 1);
    }

    float acc;

    // ---- EDGE ----
    stage<10, STRIDE10>(edge + e0 * 40, (float*)sbuf, tid);
    __syncthreads();   // covers weights + edge staging
    acc = mlp_sum4<10>(sbuf + tid * STRIDE10,
                       swts + O_EW1, swts + O_EB1, swts + O_EW2,
                       swts + O_EB2, swts + O_EW3, swts + O_EB3);
    __syncthreads();

    // ---- CROSS ----
    stage<8, STRIDE8>(cross + e0 * 32, (float*)sbuf, tid);
    __syncthreads();
    acc += mlp_sum4<8>(sbuf + tid * STRIDE8,
                       swts + O_XW1, swts + O_XB1, swts + O_XW2,
                       swts + O_XB2, swts + O_XW3, swts + O_XB3);
    __syncthreads();

    // ---- CORNER ----
    stage<10, STRIDE10>(corner + e0 * 40, (float*)sbuf, tid);
    __syncthreads();
    acc += mlp_sum4<10>(sbuf + tid * STRIDE10,
                        swts + O_CW1, swts + O_CB1, swts + O_CW2,
                        swts + O_CB2, swts + O_CW3, swts + O_CB3);

    // ---- cn linear + output ----
    float2 nwv = unpk(swts[O_NW]);
    float2 nbv = unpk(swts[O_NB]);
    acc += cn[e0 + tid] * nwv.x + nbv.x;
    out[e0 + tid] = acc;
}

extern "C" void kernel_launch(void* const* d_in, const int* in_sizes, int n_in,
                              void* d_out, int out_size) {
    const float* edge   = (const float*)d_in[0];
    const float* cross  = (const float*)d_in[1];
    const float* corner = (const float*)d_in[2];
    const float* cn     = (const float*)d_in[3];
    const float* eW1 = (const float*)d_in[4];
    const float* eb1 = (const float*)d_in[5];
    const float* eW2 = (const float*)d_in[6];
    const float* eb2 = (const float*)d_in[7];
    const float* eW3 = (const float*)d_in[8];
    const float* eb3 = (const float*)d_in[9];
    const float* xW1 = (const float*)d_in[10];
    const float* xb1 = (const float*)d_in[11];
    const float* xW2 = (const float*)d_in[12];
    const float* xb2 = (const float*)d_in[13];
    const float* xW3 = (const float*)d_in[14];
    const float* xb3 = (const float*)d_in[15];
    const float* cW1 = (const float*)d_in[16];
    const float* cb1 = (const float*)d_in[17];
    const float* cW2 = (const float*)d_in[18];
    const float* cb2 = (const float*)d_in[19];
    const float* cW3 = (const float*)d_in[20];
    const float* cb3 = (const float*)d_in[21];
    const float* nW  = (const float*)d_in[22];
    const float* nb  = (const float*)d_in[23];

    int B = in_sizes[0] / 40;          // edge is [B,4,10]
    int blocks = B / TPB;              // 4096

    osero_kernel<<<blocks, TPB>>>(edge, cross, corner, cn,
                                  eW1, eb1, eW2, eb2, eW3, eb3,
                                  xW1, xb1, xW2, xb2, xW3, xb3,
                                  cW1, cb1, cW2, cb2, cW3, cb3,
                                  nW, nb, (float*)d_out);
}

// round 7
// speedup vs baseline: 4.5361x; 1.0025x over previous
#include <cuda_runtime.h>

typedef unsigned long long u64;

#define TPB 256
// element strides in u64 units; 21 mod 16 = 5 (coprime 16) and 17 mod 16 = 1
// -> conflict-free LDS.64 across lanes
#define STRIDE10 21   // 20 u64 data (40 floats) + 1 pad
#define STRIDE8  17   // 16 u64 data (32 floats) + 1 pad

// ---- packed f32x2 helpers ----
__device__ __forceinline__ u64 pk2(float lo, float hi) {
    u64 r; asm("mov.b64 %0,{%1,%2};" : "=l"(r) : "f"(lo), "f"(hi)); return r;
}
__device__ __forceinline__ float2 unpk(u64 v) {
    float2 f; asm("mov.b64 {%0,%1},%2;" : "=f"(f.x), "=f"(f.y) : "l"(v)); return f;
}
__device__ __forceinline__ u64 fma2(u64 a, u64 b, u64 c) {
    u64 d; asm("fma.rn.f32x2 %0,%1,%2,%3;" : "=l"(d) : "l"(a), "l"(b), "l"(c)); return d;
}
__device__ __forceinline__ u64 relu2(u64 v) {
    float2 f = unpk(v);
    return pk2(fmaxf(f.x, 0.f), fmaxf(f.y, 0.f));
}

// ---- shared weight layout (float2-duplicated), offsets in u64 units ----
#define O_EW1 0
#define O_EB1 100
#define O_EW2 110
#define O_EB2 210
#define O_EW3 220
#define O_EB3 230
#define O_XW1 231
#define O_XB1 295
#define O_XW2 303
#define O_XB2 367
#define O_XW3 375
#define O_XB3 383
#define O_CW1 384
#define O_CB1 484
#define O_CW2 494
#define O_CB2 594
#define O_CW3 604
#define O_CB3 614
#define O_NW  615
#define O_NB  616
#define NWTS  617

// 3-layer MLP over 4 slices as two f32x2 pairs, interleaved so every weight
// LDS.64 is reused by both pairs. xe points at this element's staged u64 data:
// u64 index i*2+p holds {slice 2p, slice 2p+1} for input feature i.
template <int D>
__device__ __forceinline__ float mlp_sum4(const u64* __restrict__ xe,
                                          const u64* __restrict__ w1, const u64* __restrict__ b1,
                                          const u64* __restrict__ w2, const u64* __restrict__ b2,
                                          const u64* __restrict__ w3, const u64* __restrict__ b3) {
    u64 x0[D], x1[D], h0[D], h1[D];
#pragma unroll
    for (int i = 0; i < D; i++) { x0[i] = xe[i * 2]; x1[i] = xe[i * 2 + 1]; }
    // layer 1 + relu
#pragma unroll
    for (int o = 0; o < D; o++) {
        u64 b = b1[o], a0 = b, a1 = b;
#pragma unroll
        for (int i = 0; i < D; i++) {
            u64 w = w1[o * D + i];
            a0 = fma2(x0[i], w, a0);
            a1 = fma2(x1[i], w, a1);
        }
        h0[o] = relu2(a0); h1[o] = relu2(a1);
    }
    // layer 2 + relu (write back into x0/x1)
#pragma unroll
    for (int o = 0; o < D; o++) {
        u64 b = b2[o], a0 = b, a1 = b;
#pragma unroll
        for (int i = 0; i < D; i++) {
            u64 w = w2[o * D + i];
            a0 = fma2(h0[i], w, a0);
            a1 = fma2(h1[i], w, a1);
        }
        x0[o] = relu2(a0); x1[o] = relu2(a1);
    }
    // layer 3 (linear, out dim 1)
    u64 b = b3[0], a0 = b, a1 = b;
#pragma unroll
    for (int i = 0; i < D; i++) {
        u64 w = w3[i];
        a0 = fma2(x0[i], w, a0);
        a1 = fma2(x1[i], w, a1);
    }
    float2 f0 = unpk(a0), f1 = unpk(a1);
    return f0.x + f0.y + f1.x + f1.y;
}

// Coalesced stage of TPB elements x (4*D) floats from global into shared with
// pair-interleaved layout: element e, feature i, slice s -> e*STRIDE*2 + i*4 + s.
template <int D, int STRIDE>
__device__ __forceinline__ void stage(const float* __restrict__ g, float* __restrict__ s, int tid) {
    const float4* g4 = (const float4*)g;
#pragma unroll
    for (int k = 0; k < D; k++) {
        int f = k * TPB + tid;          // float4 index, consecutive across threads
        float4 v = g4[f];
        int elem = f / D;
        int j = f - elem * D;           // float4 within element (0..D-1)
        float vv[4] = {v.x, v.y, v.z, v.w};
        float* base = s + elem * (STRIDE * 2);
#pragma unroll
        for (int c = 0; c < 4; c++) {
            int within = j * 4 + c;     // 0..4D-1, slice-major in gmem
            int sl = within / D;
            int i  = within - sl * D;
            base[i * 4 + sl] = vv[c];
        }
    }
}

__global__ __launch_bounds__(TPB, 2)
void osero_kernel(const float* __restrict__ edge, const float* __restrict__ cross,
                  const float* __restrict__ corner, const float* __restrict__ cn,
                  const float* __restrict__ eW1, const float* __restrict__ eb1,
                  const float* __restrict__ eW2, const float* __restrict__ eb2,
                  const float* __restrict__ eW3, const float* __restrict__ eb3,
                  const float* __restrict__ xW1, const float* __restrict__ xb1,
                  const float* __restrict__ xW2, const float* __restrict__ xb2,
                  const float* __restrict__ xW3, const float* __restrict__ xb3,
                  const float* __restrict__ cW1, const float* __restrict__ cb1,
                  const float* __restrict__ cW2, const float* __restrict__ cb2,
                  const float* __restrict__ cW3, const float* __restrict__ cb3,
                  const float* __restrict__ nW, const float* __restrict__ nb,
                  float* __restrict__ out) {
    __shared__ u64 swts[NWTS];
    __shared__ u64 sbuf[TPB * STRIDE10];   // 5376 u64 = 43008 B

    const int tid = threadIdx.x;
    const long long e0 = (long long)blockIdx.x * TPB;

    // ---- stage weights, duplicated into both f32x2 lanes ----
    {
        auto cp = [&](int off, const float* src, int n) {
            for (int i = tid; i < n; i += TPB) { float v = src[i]; swts[off + i] = pk2(v, v); }
        };
        cp(O_EW1, eW1, 100); cp(O_EB1, eb1, 10);
        cp(O_EW2, eW2, 100); cp(O_EB2, eb2, 10);
        cp(O_EW3, eW3, 10);  cp(O_EB3, eb3, 1);
        cp(O_XW1, xW1, 64);  cp(O_XB1, xb1, 8);
        cp(O_XW2, xW2, 64);  cp(O_XB2, xb2, 8);
        cp(O_XW3, xW3, 8);   cp(O_XB3, xb3, 1);
        cp(O_CW1, cW1, 100); cp(O_CB1, cb1, 10);
        cp(O_CW2, cW2, 100); cp(O_CB2, cb2, 10);
        cp(O_CW3, cW3, 10);  cp(O_CB3, cb3, 1);
        cp(O_NW, nW, 1);     cp(O_NB, nb, 1);
    }

    float acc;

    // ---- EDGE ----
    stage<10, STRIDE10>(edge + e0 * 40, (float*)sbuf, tid);
    __syncthreads();   // covers weights + edge staging
    acc = mlp_sum4<10>(sbuf + tid * STRIDE10,
                       swts + O_EW1, swts + O_EB1, swts + O_EW2,
                       swts + O_EB2, swts + O_EW3, swts + O_EB3);
    __syncthreads();

    // ---- CROSS ----
    stage<8, STRIDE8>(cross + e0 * 32, (float*)sbuf, tid);
    __syncthreads();
    acc += mlp_sum4<8>(sbuf + tid * STRIDE8,
                       swts + O_XW1, swts + O_XB1, swts + O_XW2,
                       swts + O_XB2, swts + O_XW3, swts + O_XB3);
    __syncthreads();

    // ---- CORNER ----
    stage<10, STRIDE10>(corner + e0 * 40, (float*)sbuf, tid);
    __syncthreads();
    acc += mlp_sum4<10>(sbuf + tid * STRIDE10,
                        swts + O_CW1, swts + O_CB1, swts + O_CW2,
                        swts + O_CB2, swts + O_CW3, swts + O_CB3);

    // ---- cn linear + output ----
    float2 nwv = unpk(swts[O_NW]);
    float2 nbv = unpk(swts[O_NB]);
    acc += cn[e0 + tid] * nwv.x + nbv.x;
    out[e0 + tid] = acc;
}

extern "C" void kernel_launch(void* const* d_in, const int* in_sizes, int n_in,
                              void* d_out, int out_size) {
    const float* edge   = (const float*)d_in[0];
    const float* cross  = (const float*)d_in[1];
    const float* corner = (const float*)d_in[2];
    const float* cn     = (const float*)d_in[3];
    const float* eW1 = (const float*)d_in[4];
    const float* eb1 = (const float*)d_in[5];
    const float* eW2 = (const float*)d_in[6];
    const float* eb2 = (const float*)d_in[7];
    const float* eW3 = (const float*)d_in[8];
    const float* eb3 = (const float*)d_in[9];
    const float* xW1 = (const float*)d_in[10];
    const float* xb1 = (const float*)d_in[11];
    const float* xW2 = (const float*)d_in[12];
    const float* xb2 = (const float*)d_in[13];
    const float* xW3 = (const float*)d_in[14];
    const float* xb3 = (const float*)d_in[15];
    const float* cW1 = (const float*)d_in[16];
    const float* cb1 = (const float*)d_in[17];
    const float* cW2 = (const float*)d_in[18];
    const float* cb2 = (const float*)d_in[19];
    const float* cW3 = (const float*)d_in[20];
    const float* cb3 = (const float*)d_in[21];
    const float* nW  = (const float*)d_in[22];
    const float* nb  = (const float*)d_in[23];

    int B = in_sizes[0] / 40;          // edge is [B,4,10]
    int blocks = B / TPB;              // 4096

    osero_kernel<<<blocks, TPB>>>(edge, cross, corner, cn,
                                  eW1, eb1, eW2, eb2, eW3, eb3,
                                  xW1, xb1, xW2, xb2, xW3, xb3,
                                  cW1, cb1, cW2, cb2, cW3, cb3,
                                  nW, nb, (float*)d_out);
}